// round 2
// baseline (speedup 1.0000x reference)
#include <cuda_runtime.h>
#include <cuda_bf16.h>
#include <cstdint>

#define N_NODES 100000
#define D 128

// ---------------- scratch (device globals: no allocations allowed) ----------
__device__ int   g_rowptr[N_NODES + 1];
__device__ float g_hW[(size_t)N_NODES * D];   // h @ W.T, 51.2 MB

// ---------------- Kernel 1: row_ptr via binary search -----------------------
__global__ void rowptr_kernel(const int* __restrict__ rows, int n_edges) {
    int i = blockIdx.x * blockDim.x + threadIdx.x;
    if (i > N_NODES) return;
    // lower_bound: first e with rows[e] >= i
    int lo = 0, hi = n_edges;
    while (lo < hi) {
        int mid = (lo + hi) >> 1;
        if (__ldg(&rows[mid]) < i) lo = mid + 1; else hi = mid;
    }
    g_rowptr[i] = lo;
}

// ---------------- Kernel 2: g = h @ W.T (fp32) ------------------------------
// Block: 256 threads. Tile: 32 rows x 128 cols. K processed in 2 chunks of 64
// so static smem stays under 48 KB (no cudaFuncSetAttribute needed).
// Thread t: n = t & 127 (output column), mm = t >> 7; computes 16 rows.
// Pad 68: W-operand LDS.128 at worst 2-way conflict; A-operand is broadcast.
#define GPAD 68
#define KCHUNK 64
#define GEMM_ROWS 32

__global__ void __launch_bounds__(256, 2) gemm_kernel(
    const float* __restrict__ A,   // h  [N_NODES, 128]
    const float* __restrict__ W)   // W  [128, 128]
{
    __shared__ float Ws[128 * GPAD];        // [128][68]
    __shared__ float As[GEMM_ROWS * GPAD];  // [32][68]

    const int tid    = threadIdx.x;
    const int m_base = blockIdx.x * GEMM_ROWS;

    const int n  = tid & 127;
    const int mm = tid >> 7;              // 0 or 1

    float acc[16];
    #pragma unroll
    for (int i = 0; i < 16; i++) acc[i] = 0.f;

    #pragma unroll
    for (int kc = 0; kc < 2; kc++) {
        // Load W chunk: 128 rows x 64 cols = 2048 float4, 8 per thread.
        #pragma unroll
        for (int q = 0; q < 8; q++) {
            int idx = q * 256 + tid;          // 0..2047
            int r   = idx >> 4;               // W row (0..127)
            int k4  = idx & 15;               // float4 index within chunk
            float4 v = __ldg(&((const float4*)W)[r * 32 + kc * 16 + k4]);
            *(float4*)&Ws[r * GPAD + k4 * 4] = v;
        }
        // Load A chunk: 32 rows x 64 cols = 512 float4, 2 per thread.
        #pragma unroll
        for (int q = 0; q < 2; q++) {
            int idx = q * 256 + tid;          // 0..511
            int m   = idx >> 4;
            int k4  = idx & 15;
            float4 v = __ldg(&((const float4*)A)[(size_t)(m_base + m) * 32 + kc * 16 + k4]);
            *(float4*)&As[m * GPAD + k4 * 4] = v;
        }
        __syncthreads();

        const float* as_base = &As[(mm * 16) * GPAD];

        #pragma unroll
        for (int k = 0; k < KCHUNK; k += 4) {
            float4 w = *(const float4*)&Ws[n * GPAD + k];
            #pragma unroll
            for (int i = 0; i < 16; i++) {
                float4 a = *(const float4*)&as_base[i * GPAD + k];
                acc[i] = fmaf(a.x, w.x, acc[i]);
                acc[i] = fmaf(a.y, w.y, acc[i]);
                acc[i] = fmaf(a.z, w.z, acc[i]);
                acc[i] = fmaf(a.w, w.w, acc[i]);
            }
        }
        __syncthreads();
    }

    #pragma unroll
    for (int i = 0; i < 16; i++) {
        int m = m_base + mm * 16 + i;
        g_hW[(size_t)m * D + n] = acc[i];
    }
}

// ---------------- Kernel 3: SpMM over g, fused +b and ReLU ------------------
// Warp per node; lane l owns features [4l, 4l+4). Edge chunks of 32:
// coalesced loads of (col, val), then shfl-broadcast per edge.
__global__ void __launch_bounds__(256) spmm_kernel(
    const int*   __restrict__ cols,
    const float* __restrict__ vals,
    const float* __restrict__ bias,
    float*       __restrict__ out)
{
    const int warp_id = (blockIdx.x * blockDim.x + threadIdx.x) >> 5;
    const int lane    = threadIdx.x & 31;
    if (warp_id >= N_NODES) return;

    const int start = g_rowptr[warp_id];
    const int end   = g_rowptr[warp_id + 1];

    const float4* __restrict__ g4 = (const float4*)g_hW;

    float4 acc = make_float4(0.f, 0.f, 0.f, 0.f);

    int e = start;
    // Full 32-edge chunks
    for (; e + 32 <= end; e += 32) {
        int   c = __ldg(&cols[e + lane]);
        float v = __ldg(&vals[e + lane]);
        #pragma unroll
        for (int j = 0; j < 32; j++) {
            int   cj = __shfl_sync(0xffffffffu, c, j);
            float vj = __shfl_sync(0xffffffffu, v, j);
            float4 gv = __ldg(&g4[(size_t)cj * 32 + lane]);
            acc.x = fmaf(vj, gv.x, acc.x);
            acc.y = fmaf(vj, gv.y, acc.y);
            acc.z = fmaf(vj, gv.z, acc.z);
            acc.w = fmaf(vj, gv.w, acc.w);
        }
    }
    // Remainder
    if (e < end) {
        int rem = end - e;
        int   c = 0; float v = 0.f;
        if (lane < rem) { c = __ldg(&cols[e + lane]); v = __ldg(&vals[e + lane]); }
        for (int j = 0; j < rem; j++) {
            int   cj = __shfl_sync(0xffffffffu, c, j);
            float vj = __shfl_sync(0xffffffffu, v, j);
            float4 gv = __ldg(&g4[(size_t)cj * 32 + lane]);
            acc.x = fmaf(vj, gv.x, acc.x);
            acc.y = fmaf(vj, gv.y, acc.y);
            acc.z = fmaf(vj, gv.z, acc.z);
            acc.w = fmaf(vj, gv.w, acc.w);
        }
    }

    float4 b4 = __ldg(&((const float4*)bias)[lane]);
    acc.x = fmaxf(acc.x + b4.x, 0.f);
    acc.y = fmaxf(acc.y + b4.y, 0.f);
    acc.z = fmaxf(acc.z + b4.z, 0.f);
    acc.w = fmaxf(acc.w + b4.w, 0.f);

    ((float4*)out)[(size_t)warp_id * 32 + lane] = acc;
}

// ---------------- launch ----------------------------------------------------
extern "C" void kernel_launch(void* const* d_in, const int* in_sizes, int n_in,
                              void* d_out, int out_size)
{
    const int*   edge_rows = (const int*)  d_in[0];
    const int*   edge_cols = (const int*)  d_in[1];
    const float* edge_vals = (const float*)d_in[2];
    const float* h         = (const float*)d_in[3];
    const float* W         = (const float*)d_in[4];
    const float* b         = (const float*)d_in[5];
    float*       out       = (float*)d_out;

    const int n_edges = in_sizes[0];

    // 1) row_ptr
    {
        int threads = 256;
        int blocks  = (N_NODES + 1 + threads - 1) / threads;
        rowptr_kernel<<<blocks, threads>>>(edge_rows, n_edges);
    }

    // 2) g = h @ W.T  (writes g_hW directly)
    {
        int blocks = N_NODES / GEMM_ROWS;   // 100000 / 32 = 3125 exact
        gemm_kernel<<<blocks, 256>>>(h, W);
    }

    // 3) SpMM + bias + relu
    {
        int warps_per_block = 8;             // 256 threads
        int blocks = (N_NODES + warps_per_block - 1) / warps_per_block;
        spmm_kernel<<<blocks, 256>>>(edge_cols, edge_vals, b, out);
    }
}

// round 3
// speedup vs baseline: 1.4238x; 1.4238x over previous
#include <cuda_runtime.h>
#include <cuda_bf16.h>
#include <cstdint>

#define N_NODES 100000
#define D 128

// ---------------- scratch (device globals: no allocations allowed) ----------
__device__ int   g_rowptr[N_NODES + 1];
__device__ float g_hW[(size_t)N_NODES * D];   // h @ W.T, 51.2 MB
// Pre-swizzled W fragments for mma.sync m16n8k16 (bf16 split hi/lo).
// Index: ((kstep*16 + ntile)*32 + lane) -> uint2 {b0, b1}
__device__ uint2 g_Whf[8 * 16 * 32];
__device__ uint2 g_Wlf[8 * 16 * 32];

// ---------------- Kernel 1: row_ptr via scatter over sorted rows ------------
__global__ void rowptr_kernel(const int* __restrict__ rows, int n_edges) {
    int e = blockIdx.x * blockDim.x + threadIdx.x;
    if (e >= n_edges) return;
    int b = __ldg(&rows[e]);
    if (e == 0) {
        for (int i = 0; i <= b; i++) g_rowptr[i] = 0;
    } else {
        int a = __ldg(&rows[e - 1]);
        for (int i = a + 1; i <= b; i++) g_rowptr[i] = e;
    }
    if (e == n_edges - 1) {
        for (int i = b + 1; i <= N_NODES; i++) g_rowptr[i] = n_edges;
    }
}

// ---------------- Kernel 1b: W fragment prep (bf16 hi/lo split) -------------
__device__ __forceinline__ uint32_t pack2_bf16(float x, float y) {
    __nv_bfloat162 v = __floats2bfloat162_rn(x, y);
    return *(uint32_t*)&v;
}

__global__ void wprep_kernel(const float* __restrict__ W) {
    int t = blockIdx.x * blockDim.x + threadIdx.x;   // 0..4095
    if (t >= 8 * 16 * 32) return;
    int lane  = t & 31;
    int ntile = (t >> 5) & 15;
    int kstep = t >> 9;

    int n  = ntile * 8 + (lane >> 2);
    int k0 = kstep * 16 + (lane & 3) * 2;

    float w00 = __ldg(&W[n * 128 + k0]);
    float w01 = __ldg(&W[n * 128 + k0 + 1]);
    float w10 = __ldg(&W[n * 128 + k0 + 8]);
    float w11 = __ldg(&W[n * 128 + k0 + 9]);

    __nv_bfloat16 h00 = __float2bfloat16_rn(w00);
    __nv_bfloat16 h01 = __float2bfloat16_rn(w01);
    __nv_bfloat16 h10 = __float2bfloat16_rn(w10);
    __nv_bfloat16 h11 = __float2bfloat16_rn(w11);

    uint2 hi, lo;
    hi.x = pack2_bf16(__bfloat162float(h00), __bfloat162float(h01));
    hi.y = pack2_bf16(__bfloat162float(h10), __bfloat162float(h11));
    lo.x = pack2_bf16(w00 - __bfloat162float(h00), w01 - __bfloat162float(h01));
    lo.y = pack2_bf16(w10 - __bfloat162float(h10), w11 - __bfloat162float(h11));
    // Re-pack hi exactly as rounded bf16 (pack2_bf16 re-rounds the already-rounded
    // value -> identical bits).
    g_Whf[t] = hi;
    g_Wlf[t] = lo;
}

// ---------------- Kernel 2: g = h @ W.T via mma.sync bf16 split -------------
// Block: 128 threads (4 warps). Warp w computes rows [blk*64 + w*16, +16),
// all 128 output cols. K=128 in 8 steps of 16. 3 mma per (kstep, ntile):
// Ah*Wh + Ah*Wl + Al*Wh. Error ~2^-18 relative (fp32-grade).
__device__ __forceinline__ void mma_bf16(float* c, const uint32_t* a, uint2 b) {
    asm volatile(
        "mma.sync.aligned.m16n8k16.row.col.f32.bf16.bf16.f32 "
        "{%0,%1,%2,%3}, {%4,%5,%6,%7}, {%8,%9}, {%0,%1,%2,%3};"
        : "+f"(c[0]), "+f"(c[1]), "+f"(c[2]), "+f"(c[3])
        : "r"(a[0]), "r"(a[1]), "r"(a[2]), "r"(a[3]), "r"(b.x), "r"(b.y));
}

__global__ void __launch_bounds__(128, 4) gemm_kernel(
    const float* __restrict__ A)   // h [N_NODES, 128]
{
    const int lane = threadIdx.x & 31;
    const int warp = threadIdx.x >> 5;
    const int m0   = blockIdx.x * 64 + warp * 16;

    const int grp  = lane >> 2;       // 0..7
    const int quad = lane & 3;        // 0..3

    // Row indices for A fragments (clamped for the tail block).
    int r0 = m0 + grp;
    int r1 = m0 + grp + 8;
    int r0c = min(r0, N_NODES - 1);
    int r1c = min(r1, N_NODES - 1);

    const float2* __restrict__ A2 = (const float2*)A;   // 64 float2 per row

    float acc[16][4];
    #pragma unroll
    for (int nt = 0; nt < 16; nt++)
        #pragma unroll
        for (int i = 0; i < 4; i++) acc[nt][i] = 0.f;

    #pragma unroll
    for (int kstep = 0; kstep < 8; kstep++) {
        int kk = kstep * 8 + quad;    // float2 index: k0 = kstep*16 + quad*2

        float2 a00 = __ldg(&A2[(size_t)r0c * 64 + kk]);       // row r0, k0..k0+1
        float2 a01 = __ldg(&A2[(size_t)r0c * 64 + kk + 4]);   // row r0, k0+8..
        float2 a10 = __ldg(&A2[(size_t)r1c * 64 + kk]);
        float2 a11 = __ldg(&A2[(size_t)r1c * 64 + kk + 4]);

        __nv_bfloat16 b00x = __float2bfloat16_rn(a00.x), b00y = __float2bfloat16_rn(a00.y);
        __nv_bfloat16 b01x = __float2bfloat16_rn(a01.x), b01y = __float2bfloat16_rn(a01.y);
        __nv_bfloat16 b10x = __float2bfloat16_rn(a10.x), b10y = __float2bfloat16_rn(a10.y);
        __nv_bfloat16 b11x = __float2bfloat16_rn(a11.x), b11y = __float2bfloat16_rn(a11.y);

        uint32_t Ah[4], Al[4];
        // mma A order: a0=(r0,k0), a1=(r1,k0), a2=(r0,k0+8), a3=(r1,k0+8)
        Ah[0] = pack2_bf16(__bfloat162float(b00x), __bfloat162float(b00y));
        Ah[1] = pack2_bf16(__bfloat162float(b10x), __bfloat162float(b10y));
        Ah[2] = pack2_bf16(__bfloat162float(b01x), __bfloat162float(b01y));
        Ah[3] = pack2_bf16(__bfloat162float(b11x), __bfloat162float(b11y));
        Al[0] = pack2_bf16(a00.x - __bfloat162float(b00x), a00.y - __bfloat162float(b00y));
        Al[1] = pack2_bf16(a10.x - __bfloat162float(b10x), a10.y - __bfloat162float(b10y));
        Al[2] = pack2_bf16(a01.x - __bfloat162float(b01x), a01.y - __bfloat162float(b01y));
        Al[3] = pack2_bf16(a11.x - __bfloat162float(b11x), a11.y - __bfloat162float(b11y));

        const uint2* whf = &g_Whf[(kstep * 16) * 32 + lane];
        const uint2* wlf = &g_Wlf[(kstep * 16) * 32 + lane];

        #pragma unroll
        for (int nt = 0; nt < 16; nt++) {
            uint2 wh = whf[nt * 32];
            uint2 wl = wlf[nt * 32];
            mma_bf16(acc[nt], Ah, wh);
            mma_bf16(acc[nt], Ah, wl);
            mma_bf16(acc[nt], Al, wh);
        }
    }

    // Epilogue: c0,c1 -> (row r0, cols nt*8+quad*2..+1); c2,c3 -> row r1.
    #pragma unroll
    for (int nt = 0; nt < 16; nt++) {
        int col = nt * 8 + quad * 2;
        if (r0 < N_NODES) {
            float2 v = make_float2(acc[nt][0], acc[nt][1]);
            *(float2*)&g_hW[(size_t)r0 * D + col] = v;
        }
        if (r1 < N_NODES) {
            float2 v = make_float2(acc[nt][2], acc[nt][3]);
            *(float2*)&g_hW[(size_t)r1 * D + col] = v;
        }
    }
}

// ---------------- Kernel 3: SpMM over g, fused +b and ReLU ------------------
// Warp per node; lane l owns features [4l, 4l+4). Edge chunks of 32:
// coalesced loads of (col, val), then shfl-broadcast per edge.
__global__ void __launch_bounds__(256) spmm_kernel(
    const int*   __restrict__ cols,
    const float* __restrict__ vals,
    const float* __restrict__ bias,
    float*       __restrict__ out)
{
    const int warp_id = (blockIdx.x * blockDim.x + threadIdx.x) >> 5;
    const int lane    = threadIdx.x & 31;
    if (warp_id >= N_NODES) return;

    const int start = g_rowptr[warp_id];
    const int end   = g_rowptr[warp_id + 1];

    const float4* __restrict__ g4 = (const float4*)g_hW;

    float4 acc = make_float4(0.f, 0.f, 0.f, 0.f);

    int e = start;
    for (; e + 32 <= end; e += 32) {
        int   c = __ldg(&cols[e + lane]);
        float v = __ldg(&vals[e + lane]);
        #pragma unroll
        for (int j = 0; j < 32; j++) {
            int   cj = __shfl_sync(0xffffffffu, c, j);
            float vj = __shfl_sync(0xffffffffu, v, j);
            float4 gv = __ldg(&g4[(size_t)cj * 32 + lane]);
            acc.x = fmaf(vj, gv.x, acc.x);
            acc.y = fmaf(vj, gv.y, acc.y);
            acc.z = fmaf(vj, gv.z, acc.z);
            acc.w = fmaf(vj, gv.w, acc.w);
        }
    }
    if (e < end) {
        int rem = end - e;
        int   c = 0; float v = 0.f;
        if (lane < rem) { c = __ldg(&cols[e + lane]); v = __ldg(&vals[e + lane]); }
        for (int j = 0; j < rem; j++) {
            int   cj = __shfl_sync(0xffffffffu, c, j);
            float vj = __shfl_sync(0xffffffffu, v, j);
            float4 gv = __ldg(&g4[(size_t)cj * 32 + lane]);
            acc.x = fmaf(vj, gv.x, acc.x);
            acc.y = fmaf(vj, gv.y, acc.y);
            acc.z = fmaf(vj, gv.z, acc.z);
            acc.w = fmaf(vj, gv.w, acc.w);
        }
    }

    float4 b4 = __ldg(&((const float4*)bias)[lane]);
    acc.x = fmaxf(acc.x + b4.x, 0.f);
    acc.y = fmaxf(acc.y + b4.y, 0.f);
    acc.z = fmaxf(acc.z + b4.z, 0.f);
    acc.w = fmaxf(acc.w + b4.w, 0.f);

    ((float4*)out)[(size_t)warp_id * 32 + lane] = acc;
}

// ---------------- launch ----------------------------------------------------
extern "C" void kernel_launch(void* const* d_in, const int* in_sizes, int n_in,
                              void* d_out, int out_size)
{
    const int*   edge_rows = (const int*)  d_in[0];
    const int*   edge_cols = (const int*)  d_in[1];
    const float* edge_vals = (const float*)d_in[2];
    const float* h         = (const float*)d_in[3];
    const float* W         = (const float*)d_in[4];
    const float* b         = (const float*)d_in[5];
    float*       out       = (float*)d_out;

    const int n_edges = in_sizes[0];

    // 1) row_ptr (scatter) + W fragment prep
    {
        int threads = 256;
        int blocks  = (n_edges + threads - 1) / threads;
        rowptr_kernel<<<blocks, threads>>>(edge_rows, n_edges);
        wprep_kernel<<<16, 256>>>(W);
    }

    // 2) g = h @ W.T  (tensor cores, bf16 split)
    {
        int blocks = (N_NODES + 63) / 64;   // 1563
        gemm_kernel<<<blocks, 128>>>(h);
    }

    // 3) SpMM + bias + relu
    {
        int warps_per_block = 8;             // 256 threads
        int blocks = (N_NODES + warps_per_block - 1) / warps_per_block;
        spmm_kernel<<<blocks, 256>>>(edge_cols, edge_vals, b, out);
    }
}

// round 4
// speedup vs baseline: 1.6578x; 1.1643x over previous
#include <cuda_runtime.h>
#include <cuda_bf16.h>
#include <cuda_fp16.h>
#include <cstdint>

#define N_NODES 100000
#define D 128

// ---------------- scratch (device globals: no allocations allowed) ----------
__device__ int    g_rowptr[N_NODES + 1];
__device__ __half g_hW[(size_t)N_NODES * D];   // h @ W.T in fp16, 25.6 MB
// Pre-swizzled W fragments for mma.sync m16n8k16 (bf16 split hi/lo).
// Index: ((kstep*16 + ntile)*32 + lane) -> uint2 {b0, b1}
__device__ uint2 g_Whf[8 * 16 * 32];
__device__ uint2 g_Wlf[8 * 16 * 32];

// ---------------- Kernel 1: row_ptr via scatter over sorted rows ------------
__global__ void rowptr_kernel(const int* __restrict__ rows, int n_edges) {
    int e = blockIdx.x * blockDim.x + threadIdx.x;
    if (e >= n_edges) return;
    int b = __ldg(&rows[e]);
    if (e == 0) {
        for (int i = 0; i <= b; i++) g_rowptr[i] = 0;
    } else {
        int a = __ldg(&rows[e - 1]);
        for (int i = a + 1; i <= b; i++) g_rowptr[i] = e;
    }
    if (e == n_edges - 1) {
        for (int i = b + 1; i <= N_NODES; i++) g_rowptr[i] = n_edges;
    }
}

// ---------------- Kernel 1b: W fragment prep (bf16 hi/lo split) -------------
__device__ __forceinline__ uint32_t pack2_bf16(float x, float y) {
    __nv_bfloat162 v = __floats2bfloat162_rn(x, y);
    return *(uint32_t*)&v;
}

__global__ void wprep_kernel(const float* __restrict__ W) {
    int t = blockIdx.x * blockDim.x + threadIdx.x;   // 0..4095
    if (t >= 8 * 16 * 32) return;
    int lane  = t & 31;
    int ntile = (t >> 5) & 15;
    int kstep = t >> 9;

    int n  = ntile * 8 + (lane >> 2);
    int k0 = kstep * 16 + (lane & 3) * 2;

    float w00 = __ldg(&W[n * 128 + k0]);
    float w01 = __ldg(&W[n * 128 + k0 + 1]);
    float w10 = __ldg(&W[n * 128 + k0 + 8]);
    float w11 = __ldg(&W[n * 128 + k0 + 9]);

    __nv_bfloat16 h00 = __float2bfloat16_rn(w00);
    __nv_bfloat16 h01 = __float2bfloat16_rn(w01);
    __nv_bfloat16 h10 = __float2bfloat16_rn(w10);
    __nv_bfloat16 h11 = __float2bfloat16_rn(w11);

    uint2 hi, lo;
    hi.x = pack2_bf16(__bfloat162float(h00), __bfloat162float(h01));
    hi.y = pack2_bf16(__bfloat162float(h10), __bfloat162float(h11));
    lo.x = pack2_bf16(w00 - __bfloat162float(h00), w01 - __bfloat162float(h01));
    lo.y = pack2_bf16(w10 - __bfloat162float(h10), w11 - __bfloat162float(h11));
    g_Whf[t] = hi;
    g_Wlf[t] = lo;
}

// ---------------- Kernel 2: g = h @ W.T via mma.sync bf16 split -------------
// Block: 128 threads (4 warps). Warp w computes rows [blk*64 + w*16, +16),
// all 128 output cols. K=128 in 8 steps of 16. 3 mma per (kstep, ntile):
// Ah*Wh + Ah*Wl + Al*Wh. Split error ~1e-5; fp16 output rounding dominates.
__device__ __forceinline__ void mma_bf16(float* c, const uint32_t* a, uint2 b) {
    asm volatile(
        "mma.sync.aligned.m16n8k16.row.col.f32.bf16.bf16.f32 "
        "{%0,%1,%2,%3}, {%4,%5,%6,%7}, {%8,%9}, {%0,%1,%2,%3};"
        : "+f"(c[0]), "+f"(c[1]), "+f"(c[2]), "+f"(c[3])
        : "r"(a[0]), "r"(a[1]), "r"(a[2]), "r"(a[3]), "r"(b.x), "r"(b.y));
}

__global__ void __launch_bounds__(128, 4) gemm_kernel(
    const float* __restrict__ A)   // h [N_NODES, 128]
{
    const int lane = threadIdx.x & 31;
    const int warp = threadIdx.x >> 5;
    const int m0   = blockIdx.x * 64 + warp * 16;

    const int grp  = lane >> 2;       // 0..7
    const int quad = lane & 3;        // 0..3

    int r0 = m0 + grp;
    int r1 = m0 + grp + 8;
    int r0c = min(r0, N_NODES - 1);
    int r1c = min(r1, N_NODES - 1);

    const float2* __restrict__ A2 = (const float2*)A;   // 64 float2 per row

    float acc[16][4];
    #pragma unroll
    for (int nt = 0; nt < 16; nt++)
        #pragma unroll
        for (int i = 0; i < 4; i++) acc[nt][i] = 0.f;

    #pragma unroll
    for (int kstep = 0; kstep < 8; kstep++) {
        int kk = kstep * 8 + quad;    // float2 index: k0 = kstep*16 + quad*2

        float2 a00 = __ldg(&A2[(size_t)r0c * 64 + kk]);
        float2 a01 = __ldg(&A2[(size_t)r0c * 64 + kk + 4]);
        float2 a10 = __ldg(&A2[(size_t)r1c * 64 + kk]);
        float2 a11 = __ldg(&A2[(size_t)r1c * 64 + kk + 4]);

        __nv_bfloat16 b00x = __float2bfloat16_rn(a00.x), b00y = __float2bfloat16_rn(a00.y);
        __nv_bfloat16 b01x = __float2bfloat16_rn(a01.x), b01y = __float2bfloat16_rn(a01.y);
        __nv_bfloat16 b10x = __float2bfloat16_rn(a10.x), b10y = __float2bfloat16_rn(a10.y);
        __nv_bfloat16 b11x = __float2bfloat16_rn(a11.x), b11y = __float2bfloat16_rn(a11.y);

        uint32_t Ah[4], Al[4];
        Ah[0] = pack2_bf16(__bfloat162float(b00x), __bfloat162float(b00y));
        Ah[1] = pack2_bf16(__bfloat162float(b10x), __bfloat162float(b10y));
        Ah[2] = pack2_bf16(__bfloat162float(b01x), __bfloat162float(b01y));
        Ah[3] = pack2_bf16(__bfloat162float(b11x), __bfloat162float(b11y));
        Al[0] = pack2_bf16(a00.x - __bfloat162float(b00x), a00.y - __bfloat162float(b00y));
        Al[1] = pack2_bf16(a10.x - __bfloat162float(b10x), a10.y - __bfloat162float(b10y));
        Al[2] = pack2_bf16(a01.x - __bfloat162float(b01x), a01.y - __bfloat162float(b01y));
        Al[3] = pack2_bf16(a11.x - __bfloat162float(b11x), a11.y - __bfloat162float(b11y));

        const uint2* whf = &g_Whf[(kstep * 16) * 32 + lane];
        const uint2* wlf = &g_Wlf[(kstep * 16) * 32 + lane];

        #pragma unroll
        for (int nt = 0; nt < 16; nt++) {
            uint2 wh = whf[nt * 32];
            uint2 wl = wlf[nt * 32];
            mma_bf16(acc[nt], Ah, wh);
            mma_bf16(acc[nt], Ah, wl);
            mma_bf16(acc[nt], Al, wh);
        }
    }

    // Epilogue: write fp16. c0,c1 -> (row r0, cols nt*8+quad*2..+1); c2,c3 -> r1.
    #pragma unroll
    for (int nt = 0; nt < 16; nt++) {
        int col = nt * 8 + quad * 2;
        if (r0 < N_NODES) {
            __half2 p = __floats2half2_rn(acc[nt][0], acc[nt][1]);
            *(__half2*)&g_hW[(size_t)r0 * D + col] = p;
        }
        if (r1 < N_NODES) {
            __half2 p = __floats2half2_rn(acc[nt][2], acc[nt][3]);
            *(__half2*)&g_hW[(size_t)r1 * D + col] = p;
        }
    }
}

// ---------------- Kernel 3: SpMM over fp16 g, fused +b and ReLU -------------
// Warp per node; lane l owns features [4l, 4l+4) (8 bytes fp16 per gather).
// Edge chunks of 32: coalesced loads of (col, val), shfl-broadcast per edge.
__global__ void __launch_bounds__(256) spmm_kernel(
    const int*   __restrict__ cols,
    const float* __restrict__ vals,
    const float* __restrict__ bias,
    float*       __restrict__ out)
{
    const int warp_id = (blockIdx.x * blockDim.x + threadIdx.x) >> 5;
    const int lane    = threadIdx.x & 31;
    if (warp_id >= N_NODES) return;

    const int start = g_rowptr[warp_id];
    const int end   = g_rowptr[warp_id + 1];

    const uint2* __restrict__ g2 = (const uint2*)g_hW;   // 32 uint2 per row

    float4 acc = make_float4(0.f, 0.f, 0.f, 0.f);

    int e = start;
    for (; e + 32 <= end; e += 32) {
        int   c = __ldg(&cols[e + lane]);
        float v = __ldg(&vals[e + lane]);
        #pragma unroll
        for (int j = 0; j < 32; j++) {
            int   cj = __shfl_sync(0xffffffffu, c, j);
            float vj = __shfl_sync(0xffffffffu, v, j);
            uint2 raw = __ldg(&g2[(size_t)cj * 32 + lane]);
            float2 f0 = __half22float2(*(__half2*)&raw.x);
            float2 f1 = __half22float2(*(__half2*)&raw.y);
            acc.x = fmaf(vj, f0.x, acc.x);
            acc.y = fmaf(vj, f0.y, acc.y);
            acc.z = fmaf(vj, f1.x, acc.z);
            acc.w = fmaf(vj, f1.y, acc.w);
        }
    }
    if (e < end) {
        int rem = end - e;
        int   c = 0; float v = 0.f;
        if (lane < rem) { c = __ldg(&cols[e + lane]); v = __ldg(&vals[e + lane]); }
        for (int j = 0; j < rem; j++) {
            int   cj = __shfl_sync(0xffffffffu, c, j);
            float vj = __shfl_sync(0xffffffffu, v, j);
            uint2 raw = __ldg(&g2[(size_t)cj * 32 + lane]);
            float2 f0 = __half22float2(*(__half2*)&raw.x);
            float2 f1 = __half22float2(*(__half2*)&raw.y);
            acc.x = fmaf(vj, f0.x, acc.x);
            acc.y = fmaf(vj, f0.y, acc.y);
            acc.z = fmaf(vj, f1.x, acc.z);
            acc.w = fmaf(vj, f1.y, acc.w);
        }
    }

    float4 b4 = __ldg(&((const float4*)bias)[lane]);
    acc.x = fmaxf(acc.x + b4.x, 0.f);
    acc.y = fmaxf(acc.y + b4.y, 0.f);
    acc.z = fmaxf(acc.z + b4.z, 0.f);
    acc.w = fmaxf(acc.w + b4.w, 0.f);

    ((float4*)out)[(size_t)warp_id * 32 + lane] = acc;
}

// ---------------- launch ----------------------------------------------------
extern "C" void kernel_launch(void* const* d_in, const int* in_sizes, int n_in,
                              void* d_out, int out_size)
{
    const int*   edge_rows = (const int*)  d_in[0];
    const int*   edge_cols = (const int*)  d_in[1];
    const float* edge_vals = (const float*)d_in[2];
    const float* h         = (const float*)d_in[3];
    const float* W         = (const float*)d_in[4];
    const float* b         = (const float*)d_in[5];
    float*       out       = (float*)d_out;

    const int n_edges = in_sizes[0];

    // 1) row_ptr (scatter) + W fragment prep
    {
        int threads = 256;
        int blocks  = (n_edges + threads - 1) / threads;
        rowptr_kernel<<<blocks, threads>>>(edge_rows, n_edges);
        wprep_kernel<<<16, 256>>>(W);
    }

    // 2) g = h @ W.T  (tensor cores, bf16 split, fp16 output)
    {
        int blocks = (N_NODES + 63) / 64;   // 1563
        gemm_kernel<<<blocks, 128>>>(h);
    }

    // 3) SpMM + bias + relu
    {
        int warps_per_block = 8;             // 256 threads
        int blocks = (N_NODES + warps_per_block - 1) / warps_per_block;
        spmm_kernel<<<blocks, 256>>>(edge_cols, edge_vals, b, out);
    }
}

// round 5
// speedup vs baseline: 1.6805x; 1.0137x over previous
#include <cuda_runtime.h>
#include <cuda_bf16.h>
#include <cuda_fp16.h>
#include <cstdint>

#define N_NODES 100000
#define D 128

// ---------------- scratch (device globals: no allocations allowed) ----------
__device__ int    g_rowptr[N_NODES + 1];
__device__ __half g_hW[(size_t)N_NODES * D];   // h @ W.T in fp16, 25.6 MB
// Pre-swizzled W fragments for mma.sync m16n8k16 (bf16 split hi/lo).
// Index: ((kstep*16 + ntile)*32 + lane) -> uint2 {b0, b1}
__device__ uint2 g_Whf[8 * 16 * 32];
__device__ uint2 g_Wlf[8 * 16 * 32];

// ---------------- Kernel 1: row_ptr via scatter over sorted rows ------------
__global__ void rowptr_kernel(const int* __restrict__ rows, int n_edges) {
    int e = blockIdx.x * blockDim.x + threadIdx.x;
    if (e >= n_edges) return;
    int b = __ldg(&rows[e]);
    if (e == 0) {
        for (int i = 0; i <= b; i++) g_rowptr[i] = 0;
    } else {
        int a = __ldg(&rows[e - 1]);
        for (int i = a + 1; i <= b; i++) g_rowptr[i] = e;
    }
    if (e == n_edges - 1) {
        for (int i = b + 1; i <= N_NODES; i++) g_rowptr[i] = n_edges;
    }
}

// ---------------- Kernel 1b: W fragment prep (bf16 hi/lo split) -------------
__device__ __forceinline__ uint32_t pack2_bf16(float x, float y) {
    __nv_bfloat162 v = __floats2bfloat162_rn(x, y);
    return *(uint32_t*)&v;
}

__global__ void wprep_kernel(const float* __restrict__ W) {
    int t = blockIdx.x * blockDim.x + threadIdx.x;   // 0..4095
    if (t >= 8 * 16 * 32) return;
    int lane  = t & 31;
    int ntile = (t >> 5) & 15;
    int kstep = t >> 9;

    int n  = ntile * 8 + (lane >> 2);
    int k0 = kstep * 16 + (lane & 3) * 2;

    float w00 = __ldg(&W[n * 128 + k0]);
    float w01 = __ldg(&W[n * 128 + k0 + 1]);
    float w10 = __ldg(&W[n * 128 + k0 + 8]);
    float w11 = __ldg(&W[n * 128 + k0 + 9]);

    __nv_bfloat16 h00 = __float2bfloat16_rn(w00);
    __nv_bfloat16 h01 = __float2bfloat16_rn(w01);
    __nv_bfloat16 h10 = __float2bfloat16_rn(w10);
    __nv_bfloat16 h11 = __float2bfloat16_rn(w11);

    uint2 hi, lo;
    hi.x = pack2_bf16(__bfloat162float(h00), __bfloat162float(h01));
    hi.y = pack2_bf16(__bfloat162float(h10), __bfloat162float(h11));
    lo.x = pack2_bf16(w00 - __bfloat162float(h00), w01 - __bfloat162float(h01));
    lo.y = pack2_bf16(w10 - __bfloat162float(h10), w11 - __bfloat162float(h11));
    g_Whf[t] = hi;
    g_Wlf[t] = lo;
}

// ---------------- Kernel 2: g = h @ W.T via mma.sync bf16 split -------------
// Block: 128 threads (4 warps). Warp w computes rows [blk*64 + w*16, +16),
// all 128 output cols. K=128 in 8 steps of 16. 3 mma per (kstep, ntile):
// Ah*Wh + Ah*Wl + Al*Wh. Split error ~1e-5; fp16 output rounding dominates.
__device__ __forceinline__ void mma_bf16(float* c, const uint32_t* a, uint2 b) {
    asm volatile(
        "mma.sync.aligned.m16n8k16.row.col.f32.bf16.bf16.f32 "
        "{%0,%1,%2,%3}, {%4,%5,%6,%7}, {%8,%9}, {%0,%1,%2,%3};"
        : "+f"(c[0]), "+f"(c[1]), "+f"(c[2]), "+f"(c[3])
        : "r"(a[0]), "r"(a[1]), "r"(a[2]), "r"(a[3]), "r"(b.x), "r"(b.y));
}

__global__ void __launch_bounds__(128, 4) gemm_kernel(
    const float* __restrict__ A)   // h [N_NODES, 128]
{
    const int lane = threadIdx.x & 31;
    const int warp = threadIdx.x >> 5;
    const int m0   = blockIdx.x * 64 + warp * 16;

    const int grp  = lane >> 2;       // 0..7
    const int quad = lane & 3;        // 0..3

    int r0 = m0 + grp;
    int r1 = m0 + grp + 8;
    int r0c = min(r0, N_NODES - 1);
    int r1c = min(r1, N_NODES - 1);

    const float2* __restrict__ A2 = (const float2*)A;   // 64 float2 per row

    float acc[16][4];
    #pragma unroll
    for (int nt = 0; nt < 16; nt++)
        #pragma unroll
        for (int i = 0; i < 4; i++) acc[nt][i] = 0.f;

    #pragma unroll
    for (int kstep = 0; kstep < 8; kstep++) {
        int kk = kstep * 8 + quad;    // float2 index: k0 = kstep*16 + quad*2

        float2 a00 = __ldg(&A2[(size_t)r0c * 64 + kk]);
        float2 a01 = __ldg(&A2[(size_t)r0c * 64 + kk + 4]);
        float2 a10 = __ldg(&A2[(size_t)r1c * 64 + kk]);
        float2 a11 = __ldg(&A2[(size_t)r1c * 64 + kk + 4]);

        __nv_bfloat16 b00x = __float2bfloat16_rn(a00.x), b00y = __float2bfloat16_rn(a00.y);
        __nv_bfloat16 b01x = __float2bfloat16_rn(a01.x), b01y = __float2bfloat16_rn(a01.y);
        __nv_bfloat16 b10x = __float2bfloat16_rn(a10.x), b10y = __float2bfloat16_rn(a10.y);
        __nv_bfloat16 b11x = __float2bfloat16_rn(a11.x), b11y = __float2bfloat16_rn(a11.y);

        uint32_t Ah[4], Al[4];
        Ah[0] = pack2_bf16(__bfloat162float(b00x), __bfloat162float(b00y));
        Ah[1] = pack2_bf16(__bfloat162float(b10x), __bfloat162float(b10y));
        Ah[2] = pack2_bf16(__bfloat162float(b01x), __bfloat162float(b01y));
        Ah[3] = pack2_bf16(__bfloat162float(b11x), __bfloat162float(b11y));
        Al[0] = pack2_bf16(a00.x - __bfloat162float(b00x), a00.y - __bfloat162float(b00y));
        Al[1] = pack2_bf16(a10.x - __bfloat162float(b10x), a10.y - __bfloat162float(b10y));
        Al[2] = pack2_bf16(a01.x - __bfloat162float(b01x), a01.y - __bfloat162float(b01y));
        Al[3] = pack2_bf16(a11.x - __bfloat162float(b11x), a11.y - __bfloat162float(b11y));

        const uint2* whf = &g_Whf[(kstep * 16) * 32 + lane];
        const uint2* wlf = &g_Wlf[(kstep * 16) * 32 + lane];

        #pragma unroll
        for (int nt = 0; nt < 16; nt++) {
            uint2 wh = whf[nt * 32];
            uint2 wl = wlf[nt * 32];
            mma_bf16(acc[nt], Ah, wh);
            mma_bf16(acc[nt], Ah, wl);
            mma_bf16(acc[nt], Al, wh);
        }
    }

    // Epilogue: write fp16. c0,c1 -> (row r0, cols nt*8+quad*2..+1); c2,c3 -> r1.
    #pragma unroll
    for (int nt = 0; nt < 16; nt++) {
        int col = nt * 8 + quad * 2;
        if (r0 < N_NODES) {
            __half2 p = __floats2half2_rn(acc[nt][0], acc[nt][1]);
            *(__half2*)&g_hW[(size_t)r0 * D + col] = p;
        }
        if (r1 < N_NODES) {
            __half2 p = __floats2half2_rn(acc[nt][2], acc[nt][3]);
            *(__half2*)&g_hW[(size_t)r1 * D + col] = p;
        }
    }
}

// ---------------- Kernel 3: SpMM over fp16 g, fused +b and ReLU -------------
// Warp per node; lane l owns features [4l, 4l+4) (8 bytes fp16 per gather).
// Edge chunks of 32: coalesced loads of (col, val), shfl-broadcast per edge.
__global__ void __launch_bounds__(256) spmm_kernel(
    const int*   __restrict__ cols,
    const float* __restrict__ vals,
    const float* __restrict__ bias,
    float*       __restrict__ out)
{
    const int warp_id = (blockIdx.x * blockDim.x + threadIdx.x) >> 5;
    const int lane    = threadIdx.x & 31;
    if (warp_id >= N_NODES) return;

    const int start = g_rowptr[warp_id];
    const int end   = g_rowptr[warp_id + 1];

    const uint2* __restrict__ g2 = (const uint2*)g_hW;   // 32 uint2 per row

    float4 acc = make_float4(0.f, 0.f, 0.f, 0.f);

    int e = start;
    for (; e + 32 <= end; e += 32) {
        int   c = __ldg(&cols[e + lane]);
        float v = __ldg(&vals[e + lane]);
        #pragma unroll
        for (int j = 0; j < 32; j++) {
            int   cj = __shfl_sync(0xffffffffu, c, j);
            float vj = __shfl_sync(0xffffffffu, v, j);
            uint2 raw = __ldg(&g2[(size_t)cj * 32 + lane]);
            float2 f0 = __half22float2(*(__half2*)&raw.x);
            float2 f1 = __half22float2(*(__half2*)&raw.y);
            acc.x = fmaf(vj, f0.x, acc.x);
            acc.y = fmaf(vj, f0.y, acc.y);
            acc.z = fmaf(vj, f1.x, acc.z);
            acc.w = fmaf(vj, f1.y, acc.w);
        }
    }
    if (e < end) {
        int rem = end - e;
        int   c = 0; float v = 0.f;
        if (lane < rem) { c = __ldg(&cols[e + lane]); v = __ldg(&vals[e + lane]); }
        for (int j = 0; j < rem; j++) {
            int   cj = __shfl_sync(0xffffffffu, c, j);
            float vj = __shfl_sync(0xffffffffu, v, j);
            uint2 raw = __ldg(&g2[(size_t)cj * 32 + lane]);
            float2 f0 = __half22float2(*(__half2*)&raw.x);
            float2 f1 = __half22float2(*(__half2*)&raw.y);
            acc.x = fmaf(vj, f0.x, acc.x);
            acc.y = fmaf(vj, f0.y, acc.y);
            acc.z = fmaf(vj, f1.x, acc.z);
            acc.w = fmaf(vj, f1.y, acc.w);
        }
    }

    float4 b4 = __ldg(&((const float4*)bias)[lane]);
    acc.x = fmaxf(acc.x + b4.x, 0.f);
    acc.y = fmaxf(acc.y + b4.y, 0.f);
    acc.z = fmaxf(acc.z + b4.z, 0.f);
    acc.w = fmaxf(acc.w + b4.w, 0.f);

    ((float4*)out)[(size_t)warp_id * 32 + lane] = acc;
}

// ---------------- launch ----------------------------------------------------
extern "C" void kernel_launch(void* const* d_in, const int* in_sizes, int n_in,
                              void* d_out, int out_size)
{
    const int*   edge_rows = (const int*)  d_in[0];
    const int*   edge_cols = (const int*)  d_in[1];
    const float* edge_vals = (const float*)d_in[2];
    const float* h         = (const float*)d_in[3];
    const float* W         = (const float*)d_in[4];
    const float* b         = (const float*)d_in[5];
    float*       out       = (float*)d_out;

    const int n_edges = in_sizes[0];

    // 1) row_ptr (scatter) + W fragment prep
    {
        int threads = 256;
        int blocks  = (n_edges + threads - 1) / threads;
        rowptr_kernel<<<blocks, threads>>>(edge_rows, n_edges);
        wprep_kernel<<<16, 256>>>(W);
    }

    // 2) g = h @ W.T  (tensor cores, bf16 split, fp16 output)
    {
        int blocks = (N_NODES + 63) / 64;   // 1563
        gemm_kernel<<<blocks, 128>>>(h);
    }

    // 3) SpMM + bias + relu
    {
        int warps_per_block = 8;             // 256 threads
        int blocks = (N_NODES + warps_per_block - 1) / warps_per_block;
        spmm_kernel<<<blocks, 256>>>(edge_cols, edge_vals, b, out);
    }
}

// round 7
// speedup vs baseline: 2.2002x; 1.3093x over previous
#include <cuda_runtime.h>
#include <cuda_bf16.h>
#include <cuda_fp16.h>
#include <cstdint>

#define N_NODES 100000
#define D 128

// ---------------- scratch (device globals: no allocations allowed) ----------
__device__ int    g_rowptr[N_NODES + 1];
__device__ __half g_hW[(size_t)N_NODES * D];   // h @ W.T in fp16, 25.6 MB
// Pre-swizzled W fragments for mma.sync m16n8k16 fp16.
// Index: ((kstep*16 + ntile)*32 + lane) -> uint2 {b0, b1}
__device__ uint2 g_Whf[8 * 16 * 32];

// ---------------- Kernel 1: row_ptr via scatter over sorted rows ------------
__global__ void rowptr_kernel(const int* __restrict__ rows, int n_edges) {
    int e = blockIdx.x * blockDim.x + threadIdx.x;
    if (e >= n_edges) return;
    int b = __ldg(&rows[e]);
    if (e == 0) {
        for (int i = 0; i <= b; i++) g_rowptr[i] = 0;
    } else {
        int a = __ldg(&rows[e - 1]);
        for (int i = a + 1; i <= b; i++) g_rowptr[i] = e;
    }
    if (e == n_edges - 1) {
        for (int i = b + 1; i <= N_NODES; i++) g_rowptr[i] = n_edges;
    }
}

// ---------------- Kernel 1b: W fragment prep (fp16) -------------------------
__device__ __forceinline__ uint32_t pack2_h16(float x, float y) {
    __half2 v = __floats2half2_rn(x, y);
    return *(uint32_t*)&v;
}

__global__ void wprep_kernel(const float* __restrict__ W) {
    int t = blockIdx.x * blockDim.x + threadIdx.x;   // 0..4095
    if (t >= 8 * 16 * 32) return;
    int lane  = t & 31;
    int ntile = (t >> 5) & 15;
    int kstep = t >> 9;

    int n  = ntile * 8 + (lane >> 2);
    int k0 = kstep * 16 + (lane & 3) * 2;

    float w00 = __ldg(&W[n * 128 + k0]);
    float w01 = __ldg(&W[n * 128 + k0 + 1]);
    float w10 = __ldg(&W[n * 128 + k0 + 8]);
    float w11 = __ldg(&W[n * 128 + k0 + 9]);

    uint2 f;
    f.x = pack2_h16(w00, w01);
    f.y = pack2_h16(w10, w11);
    g_Whf[t] = f;
}

// ---------------- Kernel 2: g = h @ W.T via single fp16 mma ------------------
// Block: 128 threads (4 warps). Warp w computes rows [blk*64 + w*16, +16),
// all 128 output cols. K=128 in 8 steps of 16. 1 fp16 mma per (kstep, ntile);
// fp32 accumulate. Input-rounding error ~3.4e-4 relative (under budget).
__device__ __forceinline__ void mma_f16(float* c, const uint32_t* a, uint2 b) {
    asm volatile(
        "mma.sync.aligned.m16n8k16.row.col.f32.f16.f16.f32 "
        "{%0,%1,%2,%3}, {%4,%5,%6,%7}, {%8,%9}, {%0,%1,%2,%3};"
        : "+f"(c[0]), "+f"(c[1]), "+f"(c[2]), "+f"(c[3])
        : "r"(a[0]), "r"(a[1]), "r"(a[2]), "r"(a[3]), "r"(b.x), "r"(b.y));
}

__global__ void __launch_bounds__(128, 4) gemm_kernel(
    const float* __restrict__ A)   // h [N_NODES, 128]
{
    const int lane = threadIdx.x & 31;
    const int warp = threadIdx.x >> 5;
    const int m0   = blockIdx.x * 64 + warp * 16;

    const int grp  = lane >> 2;       // 0..7
    const int quad = lane & 3;        // 0..3

    int r0 = m0 + grp;
    int r1 = m0 + grp + 8;
    int r0c = min(r0, N_NODES - 1);
    int r1c = min(r1, N_NODES - 1);

    const float2* __restrict__ A2 = (const float2*)A;   // 64 float2 per row

    float acc[16][4];
    #pragma unroll
    for (int nt = 0; nt < 16; nt++)
        #pragma unroll
        for (int i = 0; i < 4; i++) acc[nt][i] = 0.f;

    #pragma unroll
    for (int kstep = 0; kstep < 8; kstep++) {
        int kk = kstep * 8 + quad;    // float2 index: k0 = kstep*16 + quad*2

        float2 a00 = __ldg(&A2[(size_t)r0c * 64 + kk]);       // (r0, k0..k0+1)
        float2 a01 = __ldg(&A2[(size_t)r0c * 64 + kk + 4]);   // (r0, k0+8..)
        float2 a10 = __ldg(&A2[(size_t)r1c * 64 + kk]);
        float2 a11 = __ldg(&A2[(size_t)r1c * 64 + kk + 4]);

        uint32_t Ah[4];
        // mma A order: a0=(r0,k0), a1=(r1,k0), a2=(r0,k0+8), a3=(r1,k0+8)
        Ah[0] = pack2_h16(a00.x, a00.y);
        Ah[1] = pack2_h16(a10.x, a10.y);
        Ah[2] = pack2_h16(a01.x, a01.y);
        Ah[3] = pack2_h16(a11.x, a11.y);

        const uint2* whf = &g_Whf[(kstep * 16) * 32 + lane];

        #pragma unroll
        for (int nt = 0; nt < 16; nt++) {
            uint2 wh = whf[nt * 32];
            mma_f16(acc[nt], Ah, wh);
        }
    }

    // Epilogue: write fp16. c0,c1 -> (row r0, cols nt*8+quad*2..+1); c2,c3 -> r1.
    #pragma unroll
    for (int nt = 0; nt < 16; nt++) {
        int col = nt * 8 + quad * 2;
        if (r0 < N_NODES) {
            __half2 p = __floats2half2_rn(acc[nt][0], acc[nt][1]);
            *(__half2*)&g_hW[(size_t)r0 * D + col] = p;
        }
        if (r1 < N_NODES) {
            __half2 p = __floats2half2_rn(acc[nt][2], acc[nt][3]);
            *(__half2*)&g_hW[(size_t)r1 * D + col] = p;
        }
    }
}

// ---------------- Kernel 3: SpMM over fp16 g, fused +b and ReLU -------------
// Warp per node; lane l owns features [4l, 4l+4) (8 bytes fp16 per gather).
// Edge chunks of 32: coalesced loads of (col, val), shfl-broadcast per edge.
// 32-bit index math: cj*32+lane fits well inside 32 bits (max 3.2M).
__global__ void __launch_bounds__(256) spmm_kernel(
    const int*   __restrict__ cols,
    const float* __restrict__ vals,
    const float* __restrict__ bias,
    float*       __restrict__ out)
{
    const int warp_id = (blockIdx.x * blockDim.x + threadIdx.x) >> 5;
    const int lane    = threadIdx.x & 31;
    if (warp_id >= N_NODES) return;

    const int start = g_rowptr[warp_id];
    const int end   = g_rowptr[warp_id + 1];

    const uint2* __restrict__ g2 = (const uint2*)g_hW;   // 32 uint2 per row

    float4 acc = make_float4(0.f, 0.f, 0.f, 0.f);

    int e = start;
    for (; e + 32 <= end; e += 32) {
        int   c = __ldg(&cols[e + lane]);
        float v = __ldg(&vals[e + lane]);
        #pragma unroll
        for (int j = 0; j < 32; j++) {
            unsigned cj = (unsigned)__shfl_sync(0xffffffffu, c, j);
            float    vj = __shfl_sync(0xffffffffu, v, j);
            uint2 raw = __ldg(&g2[cj * 32u + (unsigned)lane]);
            float2 f0 = __half22float2(*(__half2*)&raw.x);
            float2 f1 = __half22float2(*(__half2*)&raw.y);
            acc.x = fmaf(vj, f0.x, acc.x);
            acc.y = fmaf(vj, f0.y, acc.y);
            acc.z = fmaf(vj, f1.x, acc.z);
            acc.w = fmaf(vj, f1.y, acc.w);
        }
    }
    if (e < end) {
        int rem = end - e;
        int   c = 0; float v = 0.f;
        if (lane < rem) { c = __ldg(&cols[e + lane]); v = __ldg(&vals[e + lane]); }
        for (int j = 0; j < rem; j++) {
            unsigned cj = (unsigned)__shfl_sync(0xffffffffu, c, j);
            float    vj = __shfl_sync(0xffffffffu, v, j);
            uint2 raw = __ldg(&g2[cj * 32u + (unsigned)lane]);
            float2 f0 = __half22float2(*(__half2*)&raw.x);
            float2 f1 = __half22float2(*(__half2*)&raw.y);
            acc.x = fmaf(vj, f0.x, acc.x);
            acc.y = fmaf(vj, f0.y, acc.y);
            acc.z = fmaf(vj, f1.x, acc.z);
            acc.w = fmaf(vj, f1.y, acc.w);
        }
    }

    float4 b4 = __ldg(&((const float4*)bias)[lane]);
    acc.x = fmaxf(acc.x + b4.x, 0.f);
    acc.y = fmaxf(acc.y + b4.y, 0.f);
    acc.z = fmaxf(acc.z + b4.z, 0.f);
    acc.w = fmaxf(acc.w + b4.w, 0.f);

    ((float4*)out)[(size_t)warp_id * 32 + lane] = acc;
}

// ---------------- launch ----------------------------------------------------
extern "C" void kernel_launch(void* const* d_in, const int* in_sizes, int n_in,
                              void* d_out, int out_size)
{
    const int*   edge_rows = (const int*)  d_in[0];
    const int*   edge_cols = (const int*)  d_in[1];
    const float* edge_vals = (const float*)d_in[2];
    const float* h         = (const float*)d_in[3];
    const float* W         = (const float*)d_in[4];
    const float* b         = (const float*)d_in[5];
    float*       out       = (float*)d_out;

    const int n_edges = in_sizes[0];

    // 1) row_ptr (scatter) + W fragment prep
    {
        int threads = 256;
        int blocks  = (n_edges + threads - 1) / threads;
        rowptr_kernel<<<blocks, threads>>>(edge_rows, n_edges);
        wprep_kernel<<<16, 256>>>(W);
    }

    // 2) g = h @ W.T  (fp16 tensor cores, fp32 accumulate, fp16 output)
    {
        int blocks = (N_NODES + 63) / 64;   // 1563
        gemm_kernel<<<blocks, 128>>>(h);
    }

    // 3) SpMM + bias + relu
    {
        int warps_per_block = 8;             // 256 threads
        int blocks = (N_NODES + warps_per_block - 1) / warps_per_block;
        spmm_kernel<<<blocks, 256>>>(edge_cols, edge_vals, b, out);
    }
}

// round 8
// speedup vs baseline: 2.2009x; 1.0003x over previous
#include <cuda_runtime.h>
#include <cuda_bf16.h>
#include <cuda_fp16.h>
#include <cstdint>

#define N_NODES 100000
#define D 128

// ---------------- scratch (device globals: no allocations allowed) ----------
__device__ int    g_rowptr[N_NODES + 1];
__device__ __half g_hW[(size_t)N_NODES * D];   // h @ W.T in fp16, 25.6 MB
// Pre-swizzled W fragments for mma.sync m16n8k16 fp16.
// Index: ((kstep*16 + ntile)*32 + lane) -> uint2 {b0, b1}
__device__ uint2 g_Whf[8 * 16 * 32];

// ---------------- Kernel 1: row_ptr via scatter over sorted rows ------------
__global__ void rowptr_kernel(const int* __restrict__ rows, int n_edges) {
    int e = blockIdx.x * blockDim.x + threadIdx.x;
    if (e >= n_edges) return;
    int b = __ldg(&rows[e]);
    if (e == 0) {
        for (int i = 0; i <= b; i++) g_rowptr[i] = 0;
    } else {
        int a = __ldg(&rows[e - 1]);
        for (int i = a + 1; i <= b; i++) g_rowptr[i] = e;
    }
    if (e == n_edges - 1) {
        for (int i = b + 1; i <= N_NODES; i++) g_rowptr[i] = n_edges;
    }
}

// ---------------- Kernel 1b: W fragment prep (fp16) -------------------------
__device__ __forceinline__ uint32_t pack2_h16(float x, float y) {
    __half2 v = __floats2half2_rn(x, y);
    return *(uint32_t*)&v;
}

__global__ void wprep_kernel(const float* __restrict__ W) {
    int t = blockIdx.x * blockDim.x + threadIdx.x;   // 0..4095
    if (t >= 8 * 16 * 32) return;
    int lane  = t & 31;
    int ntile = (t >> 5) & 15;
    int kstep = t >> 9;

    int n  = ntile * 8 + (lane >> 2);
    int k0 = kstep * 16 + (lane & 3) * 2;

    float w00 = __ldg(&W[n * 128 + k0]);
    float w01 = __ldg(&W[n * 128 + k0 + 1]);
    float w10 = __ldg(&W[n * 128 + k0 + 8]);
    float w11 = __ldg(&W[n * 128 + k0 + 9]);

    uint2 f;
    f.x = pack2_h16(w00, w01);
    f.y = pack2_h16(w10, w11);
    g_Whf[t] = f;
}

// ---------------- Kernel 2: g = h @ W.T via single fp16 mma ------------------
// Block: 128 threads (4 warps). Warp w computes rows [blk*64 + w*16, +16),
// all 128 output cols. K=128 in 8 steps of 16. 1 fp16 mma per (kstep, ntile);
// fp32 accumulate. Input-rounding error ~3.4e-4 relative (under budget).
__device__ __forceinline__ void mma_f16(float* c, const uint32_t* a, uint2 b) {
    asm volatile(
        "mma.sync.aligned.m16n8k16.row.col.f32.f16.f16.f32 "
        "{%0,%1,%2,%3}, {%4,%5,%6,%7}, {%8,%9}, {%0,%1,%2,%3};"
        : "+f"(c[0]), "+f"(c[1]), "+f"(c[2]), "+f"(c[3])
        : "r"(a[0]), "r"(a[1]), "r"(a[2]), "r"(a[3]), "r"(b.x), "r"(b.y));
}

__global__ void __launch_bounds__(128, 4) gemm_kernel(
    const float* __restrict__ A)   // h [N_NODES, 128]
{
    const int lane = threadIdx.x & 31;
    const int warp = threadIdx.x >> 5;
    const int m0   = blockIdx.x * 64 + warp * 16;

    const int grp  = lane >> 2;       // 0..7
    const int quad = lane & 3;        // 0..3

    int r0 = m0 + grp;
    int r1 = m0 + grp + 8;
    int r0c = min(r0, N_NODES - 1);
    int r1c = min(r1, N_NODES - 1);

    const float2* __restrict__ A2 = (const float2*)A;   // 64 float2 per row

    float acc[16][4];
    #pragma unroll
    for (int nt = 0; nt < 16; nt++)
        #pragma unroll
        for (int i = 0; i < 4; i++) acc[nt][i] = 0.f;

    #pragma unroll
    for (int kstep = 0; kstep < 8; kstep++) {
        int kk = kstep * 8 + quad;    // float2 index: k0 = kstep*16 + quad*2

        float2 a00 = __ldg(&A2[(size_t)r0c * 64 + kk]);       // (r0, k0..k0+1)
        float2 a01 = __ldg(&A2[(size_t)r0c * 64 + kk + 4]);   // (r0, k0+8..)
        float2 a10 = __ldg(&A2[(size_t)r1c * 64 + kk]);
        float2 a11 = __ldg(&A2[(size_t)r1c * 64 + kk + 4]);

        uint32_t Ah[4];
        // mma A order: a0=(r0,k0), a1=(r1,k0), a2=(r0,k0+8), a3=(r1,k0+8)
        Ah[0] = pack2_h16(a00.x, a00.y);
        Ah[1] = pack2_h16(a10.x, a10.y);
        Ah[2] = pack2_h16(a01.x, a01.y);
        Ah[3] = pack2_h16(a11.x, a11.y);

        const uint2* whf = &g_Whf[(kstep * 16) * 32 + lane];

        #pragma unroll
        for (int nt = 0; nt < 16; nt++) {
            uint2 wh = whf[nt * 32];
            mma_f16(acc[nt], Ah, wh);
        }
    }

    // Epilogue: write fp16. c0,c1 -> (row r0, cols nt*8+quad*2..+1); c2,c3 -> r1.
    #pragma unroll
    for (int nt = 0; nt < 16; nt++) {
        int col = nt * 8 + quad * 2;
        if (r0 < N_NODES) {
            __half2 p = __floats2half2_rn(acc[nt][0], acc[nt][1]);
            *(__half2*)&g_hW[(size_t)r0 * D + col] = p;
        }
        if (r1 < N_NODES) {
            __half2 p = __floats2half2_rn(acc[nt][2], acc[nt][3]);
            *(__half2*)&g_hW[(size_t)r1 * D + col] = p;
        }
    }
}

// ---------------- Kernel 3: SpMM over fp16 g, fused +b and ReLU -------------
// Warp per node; lane l owns features [4l, 4l+4) (8 bytes fp16 per gather).
// Edge chunks of 32: coalesced loads of (col, val), shfl-broadcast per edge.
// 32-bit index math: cj*32+lane fits well inside 32 bits (max 3.2M).
__global__ void __launch_bounds__(256) spmm_kernel(
    const int*   __restrict__ cols,
    const float* __restrict__ vals,
    const float* __restrict__ bias,
    float*       __restrict__ out)
{
    const int warp_id = (blockIdx.x * blockDim.x + threadIdx.x) >> 5;
    const int lane    = threadIdx.x & 31;
    if (warp_id >= N_NODES) return;

    const int start = g_rowptr[warp_id];
    const int end   = g_rowptr[warp_id + 1];

    const uint2* __restrict__ g2 = (const uint2*)g_hW;   // 32 uint2 per row

    float4 acc = make_float4(0.f, 0.f, 0.f, 0.f);

    int e = start;
    for (; e + 32 <= end; e += 32) {
        int   c = __ldg(&cols[e + lane]);
        float v = __ldg(&vals[e + lane]);
        #pragma unroll
        for (int j = 0; j < 32; j++) {
            unsigned cj = (unsigned)__shfl_sync(0xffffffffu, c, j);
            float    vj = __shfl_sync(0xffffffffu, v, j);
            uint2 raw = __ldg(&g2[cj * 32u + (unsigned)lane]);
            float2 f0 = __half22float2(*(__half2*)&raw.x);
            float2 f1 = __half22float2(*(__half2*)&raw.y);
            acc.x = fmaf(vj, f0.x, acc.x);
            acc.y = fmaf(vj, f0.y, acc.y);
            acc.z = fmaf(vj, f1.x, acc.z);
            acc.w = fmaf(vj, f1.y, acc.w);
        }
    }
    if (e < end) {
        int rem = end - e;
        int   c = 0; float v = 0.f;
        if (lane < rem) { c = __ldg(&cols[e + lane]); v = __ldg(&vals[e + lane]); }
        for (int j = 0; j < rem; j++) {
            unsigned cj = (unsigned)__shfl_sync(0xffffffffu, c, j);
            float    vj = __shfl_sync(0xffffffffu, v, j);
            uint2 raw = __ldg(&g2[cj * 32u + (unsigned)lane]);
            float2 f0 = __half22float2(*(__half2*)&raw.x);
            float2 f1 = __half22float2(*(__half2*)&raw.y);
            acc.x = fmaf(vj, f0.x, acc.x);
            acc.y = fmaf(vj, f0.y, acc.y);
            acc.z = fmaf(vj, f1.x, acc.z);
            acc.w = fmaf(vj, f1.y, acc.w);
        }
    }

    float4 b4 = __ldg(&((const float4*)bias)[lane]);
    acc.x = fmaxf(acc.x + b4.x, 0.f);
    acc.y = fmaxf(acc.y + b4.y, 0.f);
    acc.z = fmaxf(acc.z + b4.z, 0.f);
    acc.w = fmaxf(acc.w + b4.w, 0.f);

    ((float4*)out)[(size_t)warp_id * 32 + lane] = acc;
}

// ---------------- launch ----------------------------------------------------
extern "C" void kernel_launch(void* const* d_in, const int* in_sizes, int n_in,
                              void* d_out, int out_size)
{
    const int*   edge_rows = (const int*)  d_in[0];
    const int*   edge_cols = (const int*)  d_in[1];
    const float* edge_vals = (const float*)d_in[2];
    const float* h         = (const float*)d_in[3];
    const float* W         = (const float*)d_in[4];
    const float* b         = (const float*)d_in[5];
    float*       out       = (float*)d_out;

    const int n_edges = in_sizes[0];

    // 1) row_ptr (scatter) + W fragment prep
    {
        int threads = 256;
        int blocks  = (n_edges + threads - 1) / threads;
        rowptr_kernel<<<blocks, threads>>>(edge_rows, n_edges);
        wprep_kernel<<<16, 256>>>(W);
    }

    // 2) g = h @ W.T  (fp16 tensor cores, fp32 accumulate, fp16 output)
    {
        int blocks = (N_NODES + 63) / 64;   // 1563
        gemm_kernel<<<blocks, 128>>>(h);
    }

    // 3) SpMM + bias + relu
    {
        int warps_per_block = 8;             // 256 threads
        int blocks = (N_NODES + warps_per_block - 1) / warps_per_block;
        spmm_kernel<<<blocks, 256>>>(edge_cols, edge_vals, b, out);
    }
}